// round 14
// baseline (speedup 1.0000x reference)
#include <cuda_runtime.h>
#include <cstdint>

// ============================================================================
// KronLinear via tcgen05 (sm_103a), kind::tf32, SS-mode, TMEM accumulators.
// R14 = R13 (split-warp pipeline, best: 99.5us) + queue reorder: stage-1(p)
// is issued at the TOP of iteration p, right after the epilogue LDTMs are
// issued (named bar 5, arrive from w!=0 / sync from w0, then tid0 issues).
// This puts epi-LDTM FIRST in the per-pair queue (data in ~512 cyc) instead
// of behind s1h0+s1h1 (~1536 cyc) as in R13. Ordering: X(p) stores ->
// FENCE_ASYNC -> bar3 -> MBd commit -> MBd wait(acquire) -> tid0 s1 issue.
// ============================================================================

#if defined(__CUDA_ARCH_FEAT_SM103_ALL) || defined(__CUDA_ARCH_FEAT_SM100_ALL) || \
    defined(__CUDA_ARCH_FEAT_SM101_ALL) || defined(__CUDA_ARCH_SPECIFIC__)
#define KRON_TCGEN05 1
#endif

#define NTHREADS 512

#define OFF_X    0         // 2 K-tiles x [128 rows][32 f32] = 32KB
#define OFF_BST  32768     // 2 K-tiles x [256 rows][32 f32] = 64KB
#define OFF_AST  98304     // 8 K-tiles x [ 64 rows][32 f32] = 64KB
#define OFF_S2A  163840    // 2 bufs x 32KB (each: 2 K-tiles x [128][32])
#define OFF_HDR  229376    // +0 tmem ptr, +8.. mbarriers
#define SMEM_TOTAL (229376 + 128)

#define SWZ(o) ((o) ^ (((o) >> 3) & 0x70))

// idesc: [4:6) dtype F32=1, [7:10) atype TF32=2, [10:13) btype TF32=2,
// [17:22) N>>3, [24:29) M>>4
#define IDESC1 ((1u<<4)|(2u<<7)|(2u<<10)|((128u/8)<<17)|((128u/16)<<24))   // M128 N128
#define IDESC2 ((1u<<4)|(2u<<7)|(2u<<10)|(( 64u/8)<<17)|((128u/16)<<24))   // M128 N64

__device__ __forceinline__ uint32_t cvta_smem(const void* p) {
    uint32_t a;
    asm("{ .reg .u64 t; cvta.to.shared.u64 t, %1; cvt.u32.u64 %0, t; }" : "=r"(a) : "l"(p));
    return a;
}
__device__ __forceinline__ uint32_t tf32u(float f) {
    uint32_t u; asm("cvt.rna.tf32.f32 %0, %1;" : "=r"(u) : "f"(f)); return u;
}
__device__ __forceinline__ void sts32(uint32_t a, uint32_t v) {
    asm volatile("st.shared.b32 [%0], %1;" :: "r"(a), "r"(v) : "memory");
}
__device__ __forceinline__ void sts128(uint32_t a, uint32_t x, uint32_t y, uint32_t z, uint32_t w) {
    asm volatile("st.shared.v4.b32 [%0], {%1,%2,%3,%4};" :: "r"(a), "r"(x), "r"(y), "r"(z), "r"(w) : "memory");
}

#ifdef KRON_TCGEN05

__device__ __forceinline__ void mbar_init(uint32_t a, uint32_t c) {
    asm volatile("mbarrier.init.shared.b64 [%0], %1;" :: "r"(a), "r"(c) : "memory");
}
__device__ __forceinline__ void mbar_wait(uint32_t a, uint32_t parity) {
    asm volatile(
        "{\n\t.reg .pred P;\n\t"
        "WL_%=:\n\t"
        "mbarrier.try_wait.parity.acquire.cta.shared::cta.b64 P, [%0], %1, 0x989680;\n\t"
        "@P bra.uni WD_%=;\n\t"
        "bra.uni WL_%=;\n\t"
        "WD_%=:\n\t}"
        :: "r"(a), "r"(parity) : "memory");
}

#define TC_ALLOC(sa, n)   asm volatile("tcgen05.alloc.cta_group::1.sync.aligned.shared::cta.b32 [%0], %1;" :: "r"(sa), "r"((uint32_t)(n)) : "memory")
#define TC_DEALLOC(t, n)  asm volatile("tcgen05.dealloc.cta_group::1.sync.aligned.b32 %0, %1;" :: "r"(t), "r"((uint32_t)(n)))
#define TC_WAIT_LD()      asm volatile("tcgen05.wait::ld.sync.aligned;" ::: "memory")
#define TC_FENCE_BEFORE() asm volatile("tcgen05.fence::before_thread_sync;" ::: "memory")
#define TC_FENCE_AFTER()  asm volatile("tcgen05.fence::after_thread_sync;" ::: "memory")
#define TC_COMMIT(mb)     asm volatile("tcgen05.commit.cta_group::1.mbarrier::arrive::one.shared::cluster.b64 [%0];" :: "r"(mb) : "memory")
#define FENCE_ASYNC()     asm volatile("fence.proxy.async.shared::cta;" ::: "memory")

#define BARX_SYNC(id, n)   asm volatile("bar.sync %0, %1;"   :: "r"(id), "r"(n) : "memory")
#define BARX_ARRIVE(id, n) asm volatile("bar.arrive %0, %1;" :: "r"(id), "r"(n) : "memory")

__device__ __forceinline__ uint64_t sdesc(uint32_t addr) {  // SW128, version=1, SBO=64, LBO=1
    return (uint64_t(2) << 61) | (uint64_t(1) << 46) | (uint64_t(64) << 32) |
           (uint64_t(1) << 16) | ((addr >> 4) & 0x3FFF);
}

__device__ __forceinline__ void umma(uint32_t d, uint64_t a, uint64_t b, uint32_t idesc, uint32_t en) {
    asm volatile(
        "{\n\t.reg .pred p;\n\t"
        "setp.ne.u32 p, %4, 0;\n\t"
        "tcgen05.mma.cta_group::1.kind::tf32 [%0], %1, %2, %3, {%5,%5,%5,%5}, p;\n\t}"
        :: "r"(d), "l"(a), "l"(b), "r"(idesc), "r"(en), "r"(0u) : "memory");
}

#define LDTM_X32(r, a) \
    asm volatile( \
        "tcgen05.ld.sync.aligned.32x32b.x32.b32 " \
        "{%0, %1, %2, %3, %4, %5, %6, %7, " \
        " %8, %9, %10, %11, %12, %13, %14, %15, " \
        " %16, %17, %18, %19, %20, %21, %22, %23, " \
        " %24, %25, %26, %27, %28, %29, %30, %31}, [%32];" \
        : "=r"((r)[0]),  "=r"((r)[1]),  "=r"((r)[2]),  "=r"((r)[3]), \
          "=r"((r)[4]),  "=r"((r)[5]),  "=r"((r)[6]),  "=r"((r)[7]), \
          "=r"((r)[8]),  "=r"((r)[9]),  "=r"((r)[10]), "=r"((r)[11]), \
          "=r"((r)[12]), "=r"((r)[13]), "=r"((r)[14]), "=r"((r)[15]), \
          "=r"((r)[16]), "=r"((r)[17]), "=r"((r)[18]), "=r"((r)[19]), \
          "=r"((r)[20]), "=r"((r)[21]), "=r"((r)[22]), "=r"((r)[23]), \
          "=r"((r)[24]), "=r"((r)[25]), "=r"((r)[26]), "=r"((r)[27]), \
          "=r"((r)[28]), "=r"((r)[29]), "=r"((r)[30]), "=r"((r)[31]) \
        : "r"(a))

#define LDTM_X16(r, a) \
    asm volatile( \
        "tcgen05.ld.sync.aligned.32x32b.x16.b32 " \
        "{%0, %1, %2, %3, %4, %5, %6, %7, " \
        " %8, %9, %10, %11, %12, %13, %14, %15}, [%16];" \
        : "=r"((r)[0]),  "=r"((r)[1]),  "=r"((r)[2]),  "=r"((r)[3]), \
          "=r"((r)[4]),  "=r"((r)[5]),  "=r"((r)[6]),  "=r"((r)[7]), \
          "=r"((r)[8]),  "=r"((r)[9]),  "=r"((r)[10]), "=r"((r)[11]), \
          "=r"((r)[12]), "=r"((r)[13]), "=r"((r)[14]), "=r"((r)[15]) \
        : "r"(a))

// STS: 32 D1 columns (raw fp32 bits; tf32 MMA truncates) into S2A buffer
// `buf`, K-tile (q&1), rows row0..row0+31, K-col = lane. Conflict-free.
__device__ __forceinline__ void shuffle_sts(const uint32_t* r, uint32_t sbase,
                                            int buf, int q, int row0, int lane) {
    uint32_t tile = sbase + OFF_S2A + (uint32_t)(buf * 32768 + (q & 1) * 16384);
    #pragma unroll
    for (int j = 0; j < 32; j++) {
        uint32_t off = (uint32_t)((row0 + j) * 128 + lane * 4);
        sts32(tile + SWZ(off), r[j]);
    }
}

// One K=64 r-chunk of stage 2: A = S2A buf, B = AsT tiles 2r, 2r+1.
__device__ __forceinline__ void mma_chunk(uint32_t d2, uint32_t sbase, int buf, int r, bool first) {
    #pragma unroll
    for (int s = 0; s < 8; s++) {
        uint64_t ad = sdesc(sbase + OFF_S2A + buf * 32768 + (s >> 2) * 16384) + (uint64_t)((s & 3) * 2);
        uint64_t bd = sdesc(sbase + OFF_AST + (2 * r + (s >> 2)) * 8192) + (uint64_t)((s & 3) * 2);
        umma(d2, ad, bd, IDESC2, (first && s == 0) ? 0u : 1u);
    }
}

// Stage-1 MMA, one N-half (h = 0 or 1): 8 K-steps into D1 cols 128h..128h+127.
__device__ __forceinline__ void mma_stage1_half(uint32_t d1, uint32_t sbase, int h) {
    #pragma unroll
    for (int s = 0; s < 8; s++) {
        uint64_t ad = sdesc(sbase + OFF_X + (s >> 2) * 16384) + (uint64_t)((s & 3) * 2);
        uint64_t bd = sdesc(sbase + OFF_BST + (s >> 2) * 32768) + (uint64_t)(h * 1024 + (s & 3) * 2);
        umma(d1 + h * 128, ad, bd, IDESC1, (s == 0) ? 0u : 1u);
    }
}

// X (token pair) registers -> swizzled X tiles in SMEM (512 threads, 4 vec4)
__device__ __forceinline__ void store_x(uint32_t sbase, const float4* xr, int tid) {
    #pragma unroll
    for (int t = 0; t < 4; t++) {
        int i4 = tid + t * NTHREADS, f = i4 << 2, row = f >> 6, col = f & 63;
        uint32_t addr = sbase + OFF_X + (col >> 5) * 16384 + SWZ((uint32_t)(row * 128 + (col & 31) * 4));
        sts128(addr, tf32u(xr[t].x), tf32u(xr[t].y), tf32u(xr[t].z), tf32u(xr[t].w));
    }
}

#endif // KRON_TCGEN05

__global__ void __launch_bounds__(NTHREADS, 1)
kron_tc(const float* __restrict__ x, const float* __restrict__ A,
        const float* __restrict__ B, const float* __restrict__ bias,
        float* __restrict__ out, int n_tok)
{
#ifdef KRON_TCGEN05
    extern __shared__ char smc[];
    const uint32_t sbase = cvta_smem(smc);
    const int tid  = threadIdx.x;
    const int lane = tid & 31;
    const int w    = tid >> 5;
    const int q    = w & 3;        // TMEM subpartition (lanes 32q..32q+31)
    const int cEpi = w >> 2;       // 0..3 epilogue column group
    const int grpB = w >> 3;       // 0 = group A (w0-7), 1 = group B (w8-15)
    const int c2   = (w >> 2) & 1; // chunk-within-half / S2A buffer id

    const uint32_t HDR = sbase + OFF_HDR;
    const uint32_t MBa = HDR + 8;
    const uint32_t MBc0 = HDR + 16, MBc1 = HDR + 24, MBd = HDR + 32;

    if (w == 0) TC_ALLOC(HDR, 512);
    if (tid == 0) {
        mbar_init(MBa, 1);
        mbar_init(MBc0, 1); mbar_init(MBc1, 1); mbar_init(MBd, 1);
    }
    __syncthreads();
    uint32_t tmem;
    asm volatile("ld.shared.b32 %0, [%1];" : "=r"(tmem) : "r"(HDR));
    const uint32_t D1 = tmem;          // cols 0..255
    const uint32_t D2B = tmem + 256;   // 2 bufs x 64 cols

    // per-thread epilogue bias: a2 = 16*cEpi+j, b2 = (q&1)*32+lane, tok = q>>1
    const int b2me = (q & 1) * 32 + lane;
    const int tokme = q >> 1;
    float bj[16];
    #pragma unroll
    for (int j = 0; j < 16; j++) bj[j] = bias[(16 * cEpi + j) * 64 + b2me];

    // ---- Weights (tf32-rounded, SW128 K-major tiles), once per CTA ----
    for (int i = tid; i < 256 * 64; i += NTHREADS) {
        int n = i >> 6, b = i & 63;
        uint32_t v = tf32u(B[(n & 3) * 4096 + b * 64 + (n >> 2)]);
        sts32(sbase + OFF_BST + (b >> 5) * 32768 + SWZ((uint32_t)(n * 128 + (b & 31) * 4)), v);
    }
    for (int i = tid; i < 64 * 256; i += NTHREADS) {
        int a2 = i >> 8, k = i & 255;
        uint32_t v = tf32u(A[(k >> 6) * 4096 + (k & 63) * 64 + a2]);
        sts32(sbase + OFF_AST + (k >> 5) * 8192 + SWZ((uint32_t)(a2 * 128 + (k & 31) * 4)), v);
    }

    const int np     = n_tok >> 1;
    const int stride = gridDim.x;
    int p = blockIdx.x;

    // ---- Prologue: X(p0) -> SMEM, issue stage-1(p0), commit MBa ----
    if (p < np) {
        const float4* xin = (const float4*)(x + (size_t)p * 8192);
        float4 xr[4];
        #pragma unroll
        for (int t = 0; t < 4; t++) xr[t] = xin[tid + t * NTHREADS];
        store_x(sbase, xr, tid);
    }
    FENCE_ASYNC();
    __syncthreads();
    if (tid == 0 && p < np) {
        mma_stage1_half(D1, sbase, 0);
        mma_stage1_half(D1, sbase, 1);
        TC_COMMIT(MBa);
    }

    int it = 0;
    int p_prev = -1;
    for (; p < np; p += stride, it++) {
        const uint32_t par = (uint32_t)(it & 1);
        const int  pn      = p + stride;
        const bool hasnext = pn < np;

        // prefetch next pair's X (LDGs in flight under everything below)
        float4 xr[4];
        if (hasnext) {
            const float4* xin = (const float4*)(x + (size_t)pn * 8192);
            #pragma unroll
            for (int t = 0; t < 4; t++) xr[t] = xin[tid + t * NTHREADS];
        }

        // ---- top: epilogue(prev) with epi-LDTM FIRST in the queue, then
        //      stage-1(p) issued right behind it (bar 5 gate). MBd(prev)
        //      guarantees: D2(prev) ready, S2A bufs free, all X(p) stores
        //      ordered (store_x -> bar3 -> MBd commit -> acquire wait). ----
        if (it > 0) {
            mbar_wait(MBd, par ^ 1u);
            TC_FENCE_AFTER();
            uint32_t re[16];
            LDTM_X16(re, D2B + 64 * (par ^ 1u) + 16 * cEpi);
            if (w == 0) {
                BARX_SYNC(5, 512);          // all 16 epi-LDTMs issued
                if (tid == 0) {
                    mma_stage1_half(D1, sbase, 0);   // D1(prev) reads done (bar3<MBd)
                    mma_stage1_half(D1, sbase, 1);
                    TC_COMMIT(MBa);
                }
            } else {
                BARX_ARRIVE(5, 512);
            }
            TC_WAIT_LD();
            float* orow = out + (size_t)p_prev * 8192 + tokme * 4096 + b2me;
            #pragma unroll
            for (int j = 0; j < 16; j++)
                orow[(16 * cEpi + j) * 64] = __uint_as_float(re[j]) + bj[j];
            TC_FENCE_BEFORE();
        }

        // ---- stage-1(p) done: D1 ready, X buffer free ----
        mbar_wait(MBa, par);
        TC_FENCE_AFTER();
        if (hasnext) { store_x(sbase, xr, tid); FENCE_ASYNC(); }

        uint32_t rh[32];
        const uint32_t d2 = D2B + 64 * par;

        if (grpB == 0) {
            // ===== group A: shuffle half 0 (chunk r = c2), issue r0/r1 =====
            LDTM_X32(rh, D1 + c2 * 64);
            TC_WAIT_LD();
            shuffle_sts(rh, sbase, c2, q, (q >> 1) * 64 + 0, lane);
            LDTM_X32(rh, D1 + c2 * 64 + 32);
            TC_WAIT_LD();
            BARX_ARRIVE(3, 512);          // this warp's D1-h0 reads complete
            shuffle_sts(rh, sbase, c2, q, (q >> 1) * 64 + 32, lane);
            FENCE_ASYNC();
            BARX_SYNC(1, 256);            // all A STS visible
            if (tid == 0) {
                mma_chunk(d2, sbase, 0, 0, true);  TC_COMMIT(MBc0);
                mma_chunk(d2, sbase, 1, 1, false); TC_COMMIT(MBc1);
            }
        } else {
            // ===== group B: shuffle half 1 (chunk r = 2 + c2), issue r2/r3.
            //       Overlaps group A's STS + r0/r1 MMAs. =====
            LDTM_X32(rh, D1 + 128 + c2 * 64);
            TC_WAIT_LD();
            mbar_wait(c2 ? MBc1 : MBc0, par);   // buffer c2 free (r_{c2} done)
            shuffle_sts(rh, sbase, c2, q, (q >> 1) * 64 + 0, lane);
            LDTM_X32(rh, D1 + 128 + c2 * 64 + 32);
            TC_WAIT_LD();
            shuffle_sts(rh, sbase, c2, q, (q >> 1) * 64 + 32, lane);
            FENCE_ASYNC();
            BARX_SYNC(3, 512);            // waits A's arrivals + all B warps
            if (tid == 256) {
                mma_chunk(d2, sbase, 0, 2, false);
                mma_chunk(d2, sbase, 1, 3, false);
                TC_COMMIT(MBd);
            }
        }
        p_prev = p;
    }

    // ---- final epilogue ----
    if (p_prev >= 0) {
        const uint32_t lpar = (uint32_t)((it - 1) & 1);
        mbar_wait(MBd, lpar);
        TC_FENCE_AFTER();
        uint32_t re[16];
        LDTM_X16(re, D2B + 64 * lpar + 16 * cEpi);
        TC_WAIT_LD();
        float* orow = out + (size_t)p_prev * 8192 + tokme * 4096 + b2me;
        #pragma unroll
        for (int j = 0; j < 16; j++)
            orow[(16 * cEpi + j) * 64] = __uint_as_float(re[j]) + bj[j];
    }

    __syncthreads();
    if (w == 0) TC_DEALLOC(tmem, 512);

#else  // ---------- generic fallback (compute_103 PTX pass; never selected on GB300) ----------

    extern __shared__ char smc[];
    float* Bs  = (float*)smc;           // [64][256]
    float* Asm = Bs  + 64 * 256;        // [256][64]
    float* T   = Asm + 256 * 64;        // [64][256]
    float* Xs  = T   + 64 * 256;        // [64][64]
    const int tid = threadIdx.x;

    for (int i = tid; i < 64 * 256; i += NTHREADS) {
        int b = i >> 8, cc = i & 255;
        Bs[b * 256 + cc] = __uint_as_float(tf32u(B[(cc & 3) * 4096 + b * 64 + (cc >> 2)]));
        int k = i >> 6, a2 = i & 63;
        Asm[k * 64 + a2] = __uint_as_float(tf32u(A[(k >> 6) * 4096 + (k & 63) * 64 + a2]));
    }
    __syncthreads();

    for (int tok = blockIdx.x; tok < n_tok; tok += gridDim.x) {
        for (int i = tid; i < 4096; i += NTHREADS)
            Xs[i] = __uint_as_float(tf32u(x[(size_t)tok * 4096 + i]));
        __syncthreads();
        for (int e = tid; e < 64 * 256; e += NTHREADS) {
            int a = e >> 8, cc = e & 255;
            float s = 0.f;
            for (int b = 0; b < 64; b++) s += Xs[a * 64 + b] * Bs[b * 256 + cc];
            T[a * 256 + cc] = s;
        }
        __syncthreads();
        for (int e = tid; e < 4096; e += NTHREADS) {
            int a2 = e >> 6, b2 = e & 63;
            float s = 0.f;
            for (int r = 0; r < 4; r++)
                for (int a = 0; a < 64; a++)
                    s += Asm[(r * 64 + a) * 64 + a2] * T[a * 256 + r * 64 + b2];
            out[(size_t)tok * 4096 + e] = s + bias[e];
        }
        __syncthreads();
    }
#endif
}

extern "C" void kernel_launch(void* const* d_in, const int* in_sizes, int n_in,
                              void* d_out, int out_size) {
    const float* x    = (const float*)d_in[0];
    const float* A    = (const float*)d_in[1];
    const float* B    = (const float*)d_in[2];
    const float* bias = (const float*)d_in[3];
    float* out = (float*)d_out;

    int n_tok = in_sizes[0] / 4096;
    int np = n_tok / 2;

    int dev = 0, nsm = 148;
    cudaGetDevice(&dev);
    cudaDeviceGetAttribute(&nsm, cudaDevAttrMultiProcessorCount, dev);

    cudaFuncSetAttribute(kron_tc, cudaFuncAttributeMaxDynamicSharedMemorySize, SMEM_TOTAL);

    int grid = nsm < np ? nsm : np;
    if (grid < 1) grid = 1;
    kron_tc<<<grid, NTHREADS, SMEM_TOTAL>>>(x, A, B, bias, out, n_tok);
}

// round 15
// speedup vs baseline: 1.0677x; 1.0677x over previous
#include <cuda_runtime.h>
#include <cstdint>

// ============================================================================
// KronLinear via tcgen05 (sm_103a), kind::tf32, SS-mode, TMEM accumulators.
// R15 = R13 (split-warp pipeline, best: 99.5us) + stage-1 issued as a single
// N=256 MMA sequence (8 K-step dispatches instead of 2x8 at N=128):
//   - idesc N-field is [16:23) = N/4 (SASS_QUICKREF: N=160 atom idesc[16:23]=D/4);
//     N=256 -> 64<<16. D1 cols 0..255 map to B' rows 0..255 as before.
//   - halves X SMEM re-reads (64KB -> 32KB/pair) and stage-1 dispatch count.
// Everything else identical to R13.
// ============================================================================

#if defined(__CUDA_ARCH_FEAT_SM103_ALL) || defined(__CUDA_ARCH_FEAT_SM100_ALL) || \
    defined(__CUDA_ARCH_FEAT_SM101_ALL) || defined(__CUDA_ARCH_SPECIFIC__)
#define KRON_TCGEN05 1
#endif

#define NTHREADS 512

#define OFF_X    0         // 2 K-tiles x [128 rows][32 f32] = 32KB
#define OFF_BST  32768     // 2 K-tiles x [256 rows][32 f32] = 64KB
#define OFF_AST  98304     // 8 K-tiles x [ 64 rows][32 f32] = 64KB
#define OFF_S2A  163840    // 2 bufs x 32KB (each: 2 K-tiles x [128][32])
#define OFF_HDR  229376    // +0 tmem ptr, +8.. mbarriers
#define SMEM_TOTAL (229376 + 128)

#define SWZ(o) ((o) ^ (((o) >> 3) & 0x70))

// idesc: [4:6) dtype F32=1, [7:10) atype TF32=2, [10:13) btype TF32=2,
// N-field [16:23) = N/4, [24:29) M>>4
#define IDESC1 ((1u<<4)|(2u<<7)|(2u<<10)|((256u/4)<<16)|((128u/16)<<24))   // M128 N256
#define IDESC2 ((1u<<4)|(2u<<7)|(2u<<10)|(( 64u/4)<<16)|((128u/16)<<24))   // M128 N64

__device__ __forceinline__ uint32_t cvta_smem(const void* p) {
    uint32_t a;
    asm("{ .reg .u64 t; cvta.to.shared.u64 t, %1; cvt.u32.u64 %0, t; }" : "=r"(a) : "l"(p));
    return a;
}
__device__ __forceinline__ uint32_t tf32u(float f) {
    uint32_t u; asm("cvt.rna.tf32.f32 %0, %1;" : "=r"(u) : "f"(f)); return u;
}
__device__ __forceinline__ void sts32(uint32_t a, uint32_t v) {
    asm volatile("st.shared.b32 [%0], %1;" :: "r"(a), "r"(v) : "memory");
}
__device__ __forceinline__ void sts128(uint32_t a, uint32_t x, uint32_t y, uint32_t z, uint32_t w) {
    asm volatile("st.shared.v4.b32 [%0], {%1,%2,%3,%4};" :: "r"(a), "r"(x), "r"(y), "r"(z), "r"(w) : "memory");
}

#ifdef KRON_TCGEN05

__device__ __forceinline__ void mbar_init(uint32_t a, uint32_t c) {
    asm volatile("mbarrier.init.shared.b64 [%0], %1;" :: "r"(a), "r"(c) : "memory");
}
__device__ __forceinline__ void mbar_wait(uint32_t a, uint32_t parity) {
    asm volatile(
        "{\n\t.reg .pred P;\n\t"
        "WL_%=:\n\t"
        "mbarrier.try_wait.parity.acquire.cta.shared::cta.b64 P, [%0], %1, 0x989680;\n\t"
        "@P bra.uni WD_%=;\n\t"
        "bra.uni WL_%=;\n\t"
        "WD_%=:\n\t}"
        :: "r"(a), "r"(parity) : "memory");
}

#define TC_ALLOC(sa, n)   asm volatile("tcgen05.alloc.cta_group::1.sync.aligned.shared::cta.b32 [%0], %1;" :: "r"(sa), "r"((uint32_t)(n)) : "memory")
#define TC_DEALLOC(t, n)  asm volatile("tcgen05.dealloc.cta_group::1.sync.aligned.b32 %0, %1;" :: "r"(t), "r"((uint32_t)(n)))
#define TC_WAIT_LD()      asm volatile("tcgen05.wait::ld.sync.aligned;" ::: "memory")
#define TC_FENCE_BEFORE() asm volatile("tcgen05.fence::before_thread_sync;" ::: "memory")
#define TC_FENCE_AFTER()  asm volatile("tcgen05.fence::after_thread_sync;" ::: "memory")
#define TC_COMMIT(mb)     asm volatile("tcgen05.commit.cta_group::1.mbarrier::arrive::one.shared::cluster.b64 [%0];" :: "r"(mb) : "memory")
#define FENCE_ASYNC()     asm volatile("fence.proxy.async.shared::cta;" ::: "memory")

#define BARX_SYNC(id, n)   asm volatile("bar.sync %0, %1;"   :: "r"(id), "r"(n) : "memory")
#define BARX_ARRIVE(id, n) asm volatile("bar.arrive %0, %1;" :: "r"(id), "r"(n) : "memory")

__device__ __forceinline__ uint64_t sdesc(uint32_t addr) {  // SW128, version=1, SBO=64, LBO=1
    return (uint64_t(2) << 61) | (uint64_t(1) << 46) | (uint64_t(64) << 32) |
           (uint64_t(1) << 16) | ((addr >> 4) & 0x3FFF);
}

__device__ __forceinline__ void umma(uint32_t d, uint64_t a, uint64_t b, uint32_t idesc, uint32_t en) {
    asm volatile(
        "{\n\t.reg .pred p;\n\t"
        "setp.ne.u32 p, %4, 0;\n\t"
        "tcgen05.mma.cta_group::1.kind::tf32 [%0], %1, %2, %3, {%5,%5,%5,%5}, p;\n\t}"
        :: "r"(d), "l"(a), "l"(b), "r"(idesc), "r"(en), "r"(0u) : "memory");
}

#define LDTM_X32(r, a) \
    asm volatile( \
        "tcgen05.ld.sync.aligned.32x32b.x32.b32 " \
        "{%0, %1, %2, %3, %4, %5, %6, %7, " \
        " %8, %9, %10, %11, %12, %13, %14, %15, " \
        " %16, %17, %18, %19, %20, %21, %22, %23, " \
        " %24, %25, %26, %27, %28, %29, %30, %31}, [%32];" \
        : "=r"((r)[0]),  "=r"((r)[1]),  "=r"((r)[2]),  "=r"((r)[3]), \
          "=r"((r)[4]),  "=r"((r)[5]),  "=r"((r)[6]),  "=r"((r)[7]), \
          "=r"((r)[8]),  "=r"((r)[9]),  "=r"((r)[10]), "=r"((r)[11]), \
          "=r"((r)[12]), "=r"((r)[13]), "=r"((r)[14]), "=r"((r)[15]), \
          "=r"((r)[16]), "=r"((r)[17]), "=r"((r)[18]), "=r"((r)[19]), \
          "=r"((r)[20]), "=r"((r)[21]), "=r"((r)[22]), "=r"((r)[23]), \
          "=r"((r)[24]), "=r"((r)[25]), "=r"((r)[26]), "=r"((r)[27]), \
          "=r"((r)[28]), "=r"((r)[29]), "=r"((r)[30]), "=r"((r)[31]) \
        : "r"(a))

#define LDTM_X16(r, a) \
    asm volatile( \
        "tcgen05.ld.sync.aligned.32x32b.x16.b32 " \
        "{%0, %1, %2, %3, %4, %5, %6, %7, " \
        " %8, %9, %10, %11, %12, %13, %14, %15}, [%16];" \
        : "=r"((r)[0]),  "=r"((r)[1]),  "=r"((r)[2]),  "=r"((r)[3]), \
          "=r"((r)[4]),  "=r"((r)[5]),  "=r"((r)[6]),  "=r"((r)[7]), \
          "=r"((r)[8]),  "=r"((r)[9]),  "=r"((r)[10]), "=r"((r)[11]), \
          "=r"((r)[12]), "=r"((r)[13]), "=r"((r)[14]), "=r"((r)[15]) \
        : "r"(a))

// STS: 32 D1 columns (raw fp32 bits; tf32 MMA truncates) into S2A buffer
// `buf`, K-tile (q&1), rows row0..row0+31, K-col = lane. Conflict-free.
__device__ __forceinline__ void shuffle_sts(const uint32_t* r, uint32_t sbase,
                                            int buf, int q, int row0, int lane) {
    uint32_t tile = sbase + OFF_S2A + (uint32_t)(buf * 32768 + (q & 1) * 16384);
    #pragma unroll
    for (int j = 0; j < 32; j++) {
        uint32_t off = (uint32_t)((row0 + j) * 128 + lane * 4);
        sts32(tile + SWZ(off), r[j]);
    }
}

// One K=64 r-chunk of stage 2: A = S2A buf, B = AsT tiles 2r, 2r+1.
__device__ __forceinline__ void mma_chunk(uint32_t d2, uint32_t sbase, int buf, int r, bool first) {
    #pragma unroll
    for (int s = 0; s < 8; s++) {
        uint64_t ad = sdesc(sbase + OFF_S2A + buf * 32768 + (s >> 2) * 16384) + (uint64_t)((s & 3) * 2);
        uint64_t bd = sdesc(sbase + OFF_AST + (2 * r + (s >> 2)) * 8192) + (uint64_t)((s & 3) * 2);
        umma(d2, ad, bd, IDESC2, (first && s == 0) ? 0u : 1u);
    }
}

// Stage-1 MMA, single N=256 sequence: 8 K-steps into D1 cols 0..255.
// B' tile has 256 rows x 128B per K-tile; descriptor covers the full tile.
__device__ __forceinline__ void mma_stage1(uint32_t d1, uint32_t sbase) {
    #pragma unroll
    for (int s = 0; s < 8; s++) {
        uint64_t ad = sdesc(sbase + OFF_X + (s >> 2) * 16384) + (uint64_t)((s & 3) * 2);
        uint64_t bd = sdesc(sbase + OFF_BST + (s >> 2) * 32768) + (uint64_t)((s & 3) * 2);
        umma(d1, ad, bd, IDESC1, (s == 0) ? 0u : 1u);
    }
}

// X (token pair) registers -> swizzled X tiles in SMEM (512 threads, 4 vec4)
__device__ __forceinline__ void store_x(uint32_t sbase, const float4* xr, int tid) {
    #pragma unroll
    for (int t = 0; t < 4; t++) {
        int i4 = tid + t * NTHREADS, f = i4 << 2, row = f >> 6, col = f & 63;
        uint32_t addr = sbase + OFF_X + (col >> 5) * 16384 + SWZ((uint32_t)(row * 128 + (col & 31) * 4));
        sts128(addr, tf32u(xr[t].x), tf32u(xr[t].y), tf32u(xr[t].z), tf32u(xr[t].w));
    }
}

#endif // KRON_TCGEN05

__global__ void __launch_bounds__(NTHREADS, 1)
kron_tc(const float* __restrict__ x, const float* __restrict__ A,
        const float* __restrict__ B, const float* __restrict__ bias,
        float* __restrict__ out, int n_tok)
{
#ifdef KRON_TCGEN05
    extern __shared__ char smc[];
    const uint32_t sbase = cvta_smem(smc);
    const int tid  = threadIdx.x;
    const int lane = tid & 31;
    const int w    = tid >> 5;
    const int q    = w & 3;        // TMEM subpartition (lanes 32q..32q+31)
    const int cEpi = w >> 2;       // 0..3 epilogue column group
    const int grpB = w >> 3;       // 0 = group A (w0-7), 1 = group B (w8-15)
    const int c2   = (w >> 2) & 1; // chunk-within-half / S2A buffer id

    const uint32_t HDR = sbase + OFF_HDR;
    const uint32_t MBa = HDR + 8;
    const uint32_t MBc0 = HDR + 16, MBc1 = HDR + 24, MBd = HDR + 32;

    if (w == 0) TC_ALLOC(HDR, 512);
    if (tid == 0) {
        mbar_init(MBa, 1);
        mbar_init(MBc0, 1); mbar_init(MBc1, 1); mbar_init(MBd, 1);
    }
    __syncthreads();
    uint32_t tmem;
    asm volatile("ld.shared.b32 %0, [%1];" : "=r"(tmem) : "r"(HDR));
    const uint32_t D1 = tmem;          // cols 0..255
    const uint32_t D2B = tmem + 256;   // 2 bufs x 64 cols

    // per-thread epilogue bias: a2 = 16*cEpi+j, b2 = (q&1)*32+lane, tok = q>>1
    const int b2me = (q & 1) * 32 + lane;
    const int tokme = q >> 1;
    float bj[16];
    #pragma unroll
    for (int j = 0; j < 16; j++) bj[j] = bias[(16 * cEpi + j) * 64 + b2me];

    // ---- Weights (tf32-rounded, SW128 K-major tiles), once per CTA ----
    for (int i = tid; i < 256 * 64; i += NTHREADS) {
        int n = i >> 6, b = i & 63;
        uint32_t v = tf32u(B[(n & 3) * 4096 + b * 64 + (n >> 2)]);
        sts32(sbase + OFF_BST + (b >> 5) * 32768 + SWZ((uint32_t)(n * 128 + (b & 31) * 4)), v);
    }
    for (int i = tid; i < 64 * 256; i += NTHREADS) {
        int a2 = i >> 8, k = i & 255;
        uint32_t v = tf32u(A[(k >> 6) * 4096 + (k & 63) * 64 + a2]);
        sts32(sbase + OFF_AST + (k >> 5) * 8192 + SWZ((uint32_t)(a2 * 128 + (k & 31) * 4)), v);
    }

    const int np     = n_tok >> 1;
    const int stride = gridDim.x;
    int p = blockIdx.x;

    // ---- Prologue: X(p0) -> SMEM, issue stage-1(p0) (N=256), commit MBa ----
    if (p < np) {
        const float4* xin = (const float4*)(x + (size_t)p * 8192);
        float4 xr[4];
        #pragma unroll
        for (int t = 0; t < 4; t++) xr[t] = xin[tid + t * NTHREADS];
        store_x(sbase, xr, tid);
    }
    FENCE_ASYNC();
    __syncthreads();
    if (tid == 0 && p < np) {
        mma_stage1(D1, sbase);
        TC_COMMIT(MBa);
    }

    int it = 0;
    int p_prev = -1;
    for (; p < np; p += stride, it++) {
        const uint32_t par = (uint32_t)(it & 1);
        const int  pn      = p + stride;
        const bool hasnext = pn < np;

        // prefetch next pair's X (LDGs in flight under everything below)
        float4 xr[4];
        if (hasnext) {
            const float4* xin = (const float4*)(x + (size_t)pn * 8192);
            #pragma unroll
            for (int t = 0; t < 4; t++) xr[t] = xin[tid + t * NTHREADS];
        }

        // ---- deferred epilogue (all warps): D2(prev) -> +bias -> STG.
        //      MBd(prev) also guarantees r2/r3(prev) released the S2A bufs
        //      and gates named-barrier re-arm across iterations. ----
        if (it > 0) {
            mbar_wait(MBd, par ^ 1u);
            TC_FENCE_AFTER();
            uint32_t re[16];
            LDTM_X16(re, D2B + 64 * (par ^ 1u) + 16 * cEpi);
            TC_WAIT_LD();
            float* orow = out + (size_t)p_prev * 8192 + tokme * 4096 + b2me;
            #pragma unroll
            for (int j = 0; j < 16; j++)
                orow[(16 * cEpi + j) * 64] = __uint_as_float(re[j]) + bj[j];
            TC_FENCE_BEFORE();
        }

        // ---- stage-1(p) done: D1 ready, X buffer free ----
        mbar_wait(MBa, par);
        TC_FENCE_AFTER();
        if (hasnext) { store_x(sbase, xr, tid); FENCE_ASYNC(); }

        uint32_t rh[32];
        const uint32_t d2 = D2B + 64 * par;

        if (grpB == 0) {
            // ===== group A: shuffle half 0 (chunk r = c2), issue r0/r1 =====
            LDTM_X32(rh, D1 + c2 * 64);
            TC_WAIT_LD();
            shuffle_sts(rh, sbase, c2, q, (q >> 1) * 64 + 0, lane);
            LDTM_X32(rh, D1 + c2 * 64 + 32);
            TC_WAIT_LD();
            BARX_ARRIVE(3, 512);          // this warp's D1-h0 reads complete
            shuffle_sts(rh, sbase, c2, q, (q >> 1) * 64 + 32, lane);
            FENCE_ASYNC();
            BARX_SYNC(1, 256);            // all A STS visible
            if (tid == 0) {
                mma_chunk(d2, sbase, 0, 0, true);  TC_COMMIT(MBc0);
                mma_chunk(d2, sbase, 1, 1, false); TC_COMMIT(MBc1);
            }
        } else {
            // ===== group B: shuffle half 1 (chunk r = 2 + c2), issue r2/r3,
            //       stage-1(next). Overlaps group A's STS + r0/r1 MMAs. =====
            LDTM_X32(rh, D1 + 128 + c2 * 64);
            TC_WAIT_LD();
            mbar_wait(c2 ? MBc1 : MBc0, par);   // buffer c2 free (r_{c2} done)
            shuffle_sts(rh, sbase, c2, q, (q >> 1) * 64 + 0, lane);
            LDTM_X32(rh, D1 + 128 + c2 * 64 + 32);
            TC_WAIT_LD();
            shuffle_sts(rh, sbase, c2, q, (q >> 1) * 64 + 32, lane);
            FENCE_ASYNC();
            BARX_SYNC(3, 512);            // waits A's arrivals + all B warps
            if (tid == 256) {
                mma_chunk(d2, sbase, 0, 2, false);
                mma_chunk(d2, sbase, 1, 3, false);
                TC_COMMIT(MBd);
                if (hasnext) {
                    mma_stage1(D1, sbase);      // all D1 reads done (bar 3)
                    TC_COMMIT(MBa);
                }
            }
        }
        p_prev = p;
    }

    // ---- final epilogue ----
    if (p_prev >= 0) {
        const uint32_t lpar = (uint32_t)((it - 1) & 1);
        mbar_wait(MBd, lpar);
        TC_FENCE_AFTER();
        uint32_t re[16];
        LDTM_X16(re, D2B + 64 * lpar + 16 * cEpi);
        TC_WAIT_LD();
        float* orow = out + (size_t)p_prev * 8192 + tokme * 4096 + b2me;
        #pragma unroll
        for (int j = 0; j < 16; j++)
            orow[(16 * cEpi + j) * 64] = __uint_as_float(re[j]) + bj[j];
    }

    __syncthreads();
    if (w == 0) TC_DEALLOC(tmem, 512);

#else  // ---------- generic fallback (compute_103 PTX pass; never selected on GB300) ----------

    extern __shared__ char smc[];
    float* Bs  = (float*)smc;           // [64][256]
    float* Asm = Bs  + 64 * 256;        // [256][64]
    float* T   = Asm + 256 * 64;        // [64][256]
    float* Xs  = T   + 64 * 256;        // [64][64]
    const int tid = threadIdx.x;

    for (int i = tid; i < 64 * 256; i += NTHREADS) {
        int b = i >> 8, cc = i & 255;
        Bs[b * 256 + cc] = __uint_as_float(tf32u(B[(cc & 3) * 4096 + b * 64 + (cc >> 2)]));
        int k = i >> 6, a2 = i & 63;
        Asm[k * 64 + a2] = __uint_as_float(tf32u(A[(k >> 6) * 4096 + (k & 63) * 64 + a2]));
    }
    __syncthreads();

    for (int tok = blockIdx.x; tok < n_tok; tok += gridDim.x) {
        for (int i = tid; i < 4096; i += NTHREADS)
            Xs[i] = __uint_as_float(tf32u(x[(size_t)tok * 4096 + i]));
        __syncthreads();
        for (int e = tid; e < 64 * 256; e += NTHREADS) {
            int a = e >> 8, cc = e & 255;
            float s = 0.f;
            for (int b = 0; b < 64; b++) s += Xs[a * 64 + b] * Bs[b * 256 + cc];
            T[a * 256 + cc] = s;
        }
        __syncthreads();
        for (int e = tid; e < 4096; e += NTHREADS) {
            int a2 = e >> 6, b2 = e & 63;
            float s = 0.f;
            for (int r = 0; r < 4; r++)
                for (int a = 0; a < 64; a++)
                    s += Asm[(r * 64 + a) * 64 + a2] * T[a * 256 + r * 64 + b2];
            out[(size_t)tok * 4096 + e] = s + bias[e];
        }
        __syncthreads();
    }
#endif
}

extern "C" void kernel_launch(void* const* d_in, const int* in_sizes, int n_in,
                              void* d_out, int out_size) {
    const float* x    = (const float*)d_in[0];
    const float* A    = (const float*)d_in[1];
    const float* B    = (const float*)d_in[2];
    const float* bias = (const float*)d_in[3];
    float* out = (float*)d_out;

    int n_tok = in_sizes[0] / 4096;
    int np = n_tok / 2;

    int dev = 0, nsm = 148;
    cudaGetDevice(&dev);
    cudaDeviceGetAttribute(&nsm, cudaDevAttrMultiProcessorCount, dev);

    cudaFuncSetAttribute(kron_tc, cudaFuncAttributeMaxDynamicSharedMemorySize, SMEM_TOTAL);

    int grid = nsm < np ? nsm : np;
    if (grid < 1) grid = 1;
    kron_tc<<<grid, NTHREADS, SMEM_TOTAL>>>(x, A, B, bias, out, n_tok);
}